// round 1
// baseline (speedup 1.0000x reference)
#include <cuda_runtime.h>
#include <math.h>

#define Bv 64
#define Pv 80
#define LCv 18
#define Ev 256
#define Kw 3
#define WNv 16
#define LCHv 4
#define Hv 1024
#define Dv 260
#define TAGSv 50
#define ROWS (Bv*Pv)      /* 5120 */
#define G4 (4*Hv)         /* 4096 */

// ---- scratch (device globals; no allocation allowed) ----
__device__ float g_X[ROWS*Dv];                 // combined [B*P, D] (flat == [P,B,D] flat)
__device__ float g_Gin[(size_t)ROWS*G4];       // X @ w_ih^T + b_ih + b_hh
__device__ float g_HS[(size_t)ROWS*Hv];        // h_t for all t: row (t*64+b)
__device__ float g_c[Bv*Hv];                   // LSTM cell state
__device__ float g_h0[Bv*Hv];                  // zeros (h_{-1})
__device__ float g_TS[ROWS*TAGSv];             // tag_space pre-softmax

// ---------------------------------------------------------------------------
__global__ void k_init() {
    int i = blockIdx.x * 256 + threadIdx.x;
    if (i < Bv*Hv) { g_c[i] = 0.f; g_h0[i] = 0.f; }
}

// ---- embedding + char CNN: one block per (b,p) ----------------------------
__global__ void k_embed(const int* __restrict__ sent, const int* __restrict__ chars,
                        const float* __restrict__ wemb, const float* __restrict__ cemb,
                        const float* __restrict__ convw, const float* __restrict__ convb) {
    __shared__ float ce[LCv*Ev];
    __shared__ float phi[WNv*LCHv];
    int bp = blockIdx.x;           // = b*80 + p
    int tid = threadIdx.x;

    // stage char embeddings for the 18 chars of this word
    for (int u = tid; u < LCv*Ev; u += 128) {
        int l = u >> 8, e = u & 255;
        int ci = chars[bp*LCv + l];
        ce[u] = cemb[(size_t)ci*Ev + e];
    }
    __syncthreads();

    // word embedding copy
    int wi = sent[bp];
    for (int e = tid; e < Ev; e += 128)
        g_X[(size_t)bp*Dv + e] = wemb[(size_t)wi*Ev + e];

    // conv: 16 windows x 4 channels, each a 768-dot
    if (tid < WNv*LCHv) {
        int w = tid >> 2, c = tid & 3;
        float s = convb[c];
        #pragma unroll
        for (int k = 0; k < Kw; k++) {
            const float* cw = convw + c*(Kw*Ev) + k*Ev;
            const float* cc = ce + (w + k)*Ev;
            for (int e = 0; e < Ev; e++) s += cc[e]*cw[e];
        }
        phi[w*LCHv + c] = s;
    }
    __syncthreads();
    if (tid < LCHv) {
        float m = -1e30f;
        for (int w = 0; w < WNv; w++) m = fmaxf(m, phi[w*LCHv + tid]);
        g_X[(size_t)bp*Dv + Ev + tid] = m;
    }
}

// ---- input GEMM: Gin[5120,4096] = X[5120,260] @ w_ih^T + b_ih + b_hh ------
__global__ void k_ingemm(const float* __restrict__ w_ih,
                         const float* __restrict__ b_ih,
                         const float* __restrict__ b_hh) {
    __shared__ float Xs[64][33];
    __shared__ float Ws[64][33];
    int i0 = blockIdx.y * 64;      // rows of Gin
    int j0 = blockIdx.x * 64;      // gate cols
    int tid = threadIdx.x, tx = tid & 15, ty = tid >> 4;
    float acc[4][4] = {};

    for (int k0 = 0; k0 < Dv; k0 += 32) {
        for (int u = tid; u < 64*32; u += 256) {
            int r = u >> 5, kk = u & 31, k = k0 + kk;
            Xs[r][kk] = (k < Dv) ? g_X[(size_t)(i0 + r)*Dv + k] : 0.f;
            Ws[r][kk] = (k < Dv) ? w_ih[(size_t)(j0 + r)*Dv + k] : 0.f;
        }
        __syncthreads();
        #pragma unroll
        for (int kk = 0; kk < 32; kk++) {
            float a0 = Xs[ty*4+0][kk], a1 = Xs[ty*4+1][kk],
                  a2 = Xs[ty*4+2][kk], a3 = Xs[ty*4+3][kk];
            float w0 = Ws[tx*4+0][kk], w1 = Ws[tx*4+1][kk],
                  w2 = Ws[tx*4+2][kk], w3 = Ws[tx*4+3][kk];
            acc[0][0]+=a0*w0; acc[0][1]+=a0*w1; acc[0][2]+=a0*w2; acc[0][3]+=a0*w3;
            acc[1][0]+=a1*w0; acc[1][1]+=a1*w1; acc[1][2]+=a1*w2; acc[1][3]+=a1*w3;
            acc[2][0]+=a2*w0; acc[2][1]+=a2*w1; acc[2][2]+=a2*w2; acc[2][3]+=a2*w3;
            acc[3][0]+=a3*w0; acc[3][1]+=a3*w1; acc[3][2]+=a3*w2; acc[3][3]+=a3*w3;
        }
        __syncthreads();
    }
    #pragma unroll
    for (int ii = 0; ii < 4; ii++)
        #pragma unroll
        for (int jj = 0; jj < 4; jj++) {
            int j = j0 + tx*4 + jj;
            g_Gin[(size_t)(i0 + ty*4 + ii)*G4 + j] = acc[ii][jj] + b_ih[j] + b_hh[j];
        }
}

// ---- one LSTM step: 128 blocks, each 8 h-columns (32 gate cols) -----------
__global__ void k_step(const float* __restrict__ w_hh, int t) {
    __shared__ float Hs[64][33];
    __shared__ float Wh[32][33];
    __shared__ float gsm[64][32];
    const float* hprev = (t == 0) ? g_h0 : (g_HS + (size_t)(t-1)*Bv*Hv);
    int bx = blockIdx.x;                 // j in [bx*8, bx*8+8)
    int tid = threadIdx.x, tx = tid & 15, ty = tid >> 4;
    float acc[4][2] = {};

    for (int k0 = 0; k0 < Hv; k0 += 32) {
        for (int u = tid; u < 64*32; u += 256) {
            int r = u >> 5, kk = u & 31;
            Hs[r][kk] = hprev[r*Hv + k0 + kk];
        }
        for (int u = tid; u < 32*32; u += 256) {
            int n = u >> 5, kk = u & 31;
            int gate = n >> 3, j = bx*8 + (n & 7);
            Wh[n][kk] = w_hh[(size_t)(gate*Hv + j)*Hv + k0 + kk];
        }
        __syncthreads();
        #pragma unroll
        for (int kk = 0; kk < 32; kk++) {
            float a0 = Hs[ty*4+0][kk], a1 = Hs[ty*4+1][kk],
                  a2 = Hs[ty*4+2][kk], a3 = Hs[ty*4+3][kk];
            float w0 = Wh[tx*2+0][kk], w1 = Wh[tx*2+1][kk];
            acc[0][0]+=a0*w0; acc[0][1]+=a0*w1;
            acc[1][0]+=a1*w0; acc[1][1]+=a1*w1;
            acc[2][0]+=a2*w0; acc[2][1]+=a2*w1;
            acc[3][0]+=a3*w0; acc[3][1]+=a3*w1;
        }
        __syncthreads();
    }
    // add precomputed input gates, stage to smem
    #pragma unroll
    for (int ii = 0; ii < 4; ii++)
        #pragma unroll
        for (int jj = 0; jj < 2; jj++) {
            int bb = ty*4 + ii, n = tx*2 + jj;
            int gate = n >> 3, j = bx*8 + (n & 7);
            gsm[bb][n] = acc[ii][jj] + g_Gin[(size_t)(t*Bv + bb)*G4 + gate*Hv + j];
        }
    __syncthreads();
    // activations + state update
    for (int m = tid; m < 64*8; m += 256) {
        int bb = m >> 3, jj = m & 7;
        int j = bx*8 + jj;
        float iv = gsm[bb][jj],      fv = gsm[bb][8  + jj];
        float gv = gsm[bb][16 + jj], ov = gsm[bb][24 + jj];
        float is = 1.f/(1.f + expf(-iv));
        float fs = 1.f/(1.f + expf(-fv));
        float gs = tanhf(gv);
        float os = 1.f/(1.f + expf(-ov));
        float cc = fs*g_c[bb*Hv + j] + is*gs;
        g_c[bb*Hv + j] = cc;
        g_HS[(size_t)(t*Bv + bb)*Hv + j] = os*tanhf(cc);
    }
}

// ---- head: tag_space[b,p,tg] (HS row = b*80+p, per faithful reshape) ------
__global__ void k_tag(const float* __restrict__ out_w, const float* __restrict__ out_b) {
    __shared__ float hrow[Hv];
    int bp = blockIdx.x;
    int tid = threadIdx.x;
    for (int u = tid; u < Hv; u += 256) hrow[u] = g_HS[(size_t)bp*Hv + u];
    __syncthreads();
    int warp = tid >> 5, lane = tid & 31;
    for (int tg = warp; tg < TAGSv; tg += 8) {
        float s = 0.f;
        for (int k = lane; k < Hv; k += 32) s += hrow[k]*out_w[(size_t)tg*Hv + k];
        #pragma unroll
        for (int o = 16; o; o >>= 1) s += __shfl_down_sync(0xffffffffu, s, o);
        if (lane == 0) g_TS[bp*TAGSv + tg] = s + out_b[tg];
    }
}

// ---- log_softmax over P axis ----------------------------------------------
__global__ void k_lsm(float* __restrict__ out) {
    int b = blockIdx.x;
    int tg = threadIdx.x;
    if (tg >= TAGSv) return;
    float mx = -1e30f;
    for (int p = 0; p < Pv; p++)
        mx = fmaxf(mx, g_TS[(b*Pv + p)*TAGSv + tg]);
    float s = 0.f;
    for (int p = 0; p < Pv; p++)
        s += expf(g_TS[(b*Pv + p)*TAGSv + tg] - mx);
    float l = mx + logf(s);
    for (int p = 0; p < Pv; p++)
        out[(size_t)(b*Pv + p)*TAGSv + tg] = g_TS[(b*Pv + p)*TAGSv + tg] - l;
}

// ---------------------------------------------------------------------------
extern "C" void kernel_launch(void* const* d_in, const int* in_sizes, int n_in,
                              void* d_out, int out_size) {
    const int*   sent  = (const int*)  d_in[0];
    const int*   chars = (const int*)  d_in[1];
    const float* wemb  = (const float*)d_in[2];
    const float* cemb  = (const float*)d_in[3];
    const float* convw = (const float*)d_in[4];
    const float* convb = (const float*)d_in[5];
    const float* w_ih  = (const float*)d_in[6];
    const float* w_hh  = (const float*)d_in[7];
    const float* b_ih  = (const float*)d_in[8];
    const float* b_hh  = (const float*)d_in[9];
    const float* out_w = (const float*)d_in[10];
    const float* out_b = (const float*)d_in[11];
    float* out = (float*)d_out;

    k_init<<<(Bv*Hv + 255)/256, 256>>>();
    k_embed<<<ROWS, 128>>>(sent, chars, wemb, cemb, convw, convb);
    dim3 g2(G4/64, ROWS/64);
    k_ingemm<<<g2, 256>>>(w_ih, b_ih, b_hh);
    for (int t = 0; t < Pv; t++)
        k_step<<<128, 256>>>(w_hh, t);
    k_tag<<<ROWS, 256>>>(out_w, out_b);
    k_lsm<<<Bv, 64>>>(out);
}

// round 3
// speedup vs baseline: 1.8502x; 1.8502x over previous
#include <cuda_runtime.h>
#include <math.h>

#define Bv 64
#define Pv 80
#define LCv 18
#define Ev 256
#define Kw 3
#define WNv 16
#define LCHv 4
#define Hv 1024
#define Dv 260
#define TAGSv 50
#define ROWS (Bv*Pv)      /* 5120 */
#define G4 (4*Hv)         /* 4096 */

// persistent LSTM kernel config
#define NB 128            /* blocks (<=148 SMs, 1 CTA/SM via smem) */
#define NT 256            /* threads */
#define KT 128            /* k tile for h staging */
#define WT_STRIDE 36      /* WhT row stride (floats): 16B-aligned, low conflict */
#define HS_STRIDE 132     /* Hs row stride */
#define GS_STRIDE 33

// ---- scratch (device globals; no allocation allowed) ----
__device__ float g_X[ROWS*Dv];
__device__ float g_Gin[(size_t)ROWS*G4];
__device__ float g_HS[(size_t)ROWS*Hv];
__device__ float g_TS[ROWS*TAGSv];
__device__ unsigned g_cnt;
__device__ volatile unsigned g_gen;

// ---------------------------------------------------------------------------
__global__ void k_init() {
    if (blockIdx.x == 0 && threadIdx.x == 0) { g_cnt = 0u; g_gen = 0u; }
}

// ---- embedding + char CNN: one block per (b,p) ----------------------------
__global__ void k_embed(const int* __restrict__ sent, const int* __restrict__ chars,
                        const float* __restrict__ wemb, const float* __restrict__ cemb,
                        const float* __restrict__ convw, const float* __restrict__ convb) {
    __shared__ float ce[LCv*Ev];
    __shared__ float phi[WNv*LCHv];
    int bp = blockIdx.x;
    int tid = threadIdx.x;

    for (int u = tid; u < LCv*Ev; u += 128) {
        int l = u >> 8, e = u & 255;
        int ci = chars[bp*LCv + l];
        ce[u] = cemb[(size_t)ci*Ev + e];
    }
    __syncthreads();

    int wi = sent[bp];
    for (int e = tid; e < Ev; e += 128)
        g_X[(size_t)bp*Dv + e] = wemb[(size_t)wi*Ev + e];

    if (tid < WNv*LCHv) {
        int w = tid >> 2, c = tid & 3;
        float s = convb[c];
        #pragma unroll
        for (int k = 0; k < Kw; k++) {
            const float* cw = convw + c*(Kw*Ev) + k*Ev;
            const float* cc = ce + (w + k)*Ev;
            for (int e = 0; e < Ev; e++) s += cc[e]*cw[e];
        }
        phi[w*LCHv + c] = s;
    }
    __syncthreads();
    if (tid < LCHv) {
        float m = -1e30f;
        for (int w = 0; w < WNv; w++) m = fmaxf(m, phi[w*LCHv + tid]);
        g_X[(size_t)bp*Dv + Ev + tid] = m;
    }
}

// ---- input GEMM: Gin[5120,4096] = X[5120,260] @ w_ih^T + b_ih + b_hh ------
__global__ void k_ingemm(const float* __restrict__ w_ih,
                         const float* __restrict__ b_ih,
                         const float* __restrict__ b_hh) {
    __shared__ float Xs[64][33];
    __shared__ float Ws[64][33];
    int i0 = blockIdx.y * 64;
    int j0 = blockIdx.x * 64;
    int tid = threadIdx.x, tx = tid & 15, ty = tid >> 4;
    float acc[4][4] = {};

    for (int k0 = 0; k0 < Dv; k0 += 32) {
        for (int u = tid; u < 64*32; u += 256) {
            int r = u >> 5, kk = u & 31, k = k0 + kk;
            Xs[r][kk] = (k < Dv) ? g_X[(size_t)(i0 + r)*Dv + k] : 0.f;
            Ws[r][kk] = (k < Dv) ? w_ih[(size_t)(j0 + r)*Dv + k] : 0.f;
        }
        __syncthreads();
        #pragma unroll
        for (int kk = 0; kk < 32; kk++) {
            float a0 = Xs[ty*4+0][kk], a1 = Xs[ty*4+1][kk],
                  a2 = Xs[ty*4+2][kk], a3 = Xs[ty*4+3][kk];
            float w0 = Ws[tx*4+0][kk], w1 = Ws[tx*4+1][kk],
                  w2 = Ws[tx*4+2][kk], w3 = Ws[tx*4+3][kk];
            acc[0][0]+=a0*w0; acc[0][1]+=a0*w1; acc[0][2]+=a0*w2; acc[0][3]+=a0*w3;
            acc[1][0]+=a1*w0; acc[1][1]+=a1*w1; acc[1][2]+=a1*w2; acc[1][3]+=a1*w3;
            acc[2][0]+=a2*w0; acc[2][1]+=a2*w1; acc[2][2]+=a2*w2; acc[2][3]+=a2*w3;
            acc[3][0]+=a3*w0; acc[3][1]+=a3*w1; acc[3][2]+=a3*w2; acc[3][3]+=a3*w3;
        }
        __syncthreads();
    }
    #pragma unroll
    for (int ii = 0; ii < 4; ii++)
        #pragma unroll
        for (int jj = 0; jj < 4; jj++) {
            int j = j0 + tx*4 + jj;
            g_Gin[(size_t)(i0 + ty*4 + ii)*G4 + j] = acc[ii][jj] + b_ih[j] + b_hh[j];
        }
}

// ---- persistent LSTM: whole recurrence in ONE kernel ----------------------
// Block bx owns h-cols j in [bx*8, bx*8+8) => 32 gate rows, w slice resident in smem.
__global__ void __launch_bounds__(NT, 1) k_lstm(const float* __restrict__ w_hh) {
    extern __shared__ float sm[];
    float* WhT = sm;                          // [1024][WT_STRIDE], WhT[k][n], n=gate*8+jj
    float* Hs  = WhT + Hv*WT_STRIDE;          // [64][HS_STRIDE]
    float* gsm = Hs  + Bv*HS_STRIDE;          // [64][GS_STRIDE]
    float* csm = gsm + Bv*GS_STRIDE;          // [64][8]

    const int tid = threadIdx.x, bx = blockIdx.x;
    const int j0 = bx*8;
    const int n4 = tid & 7;                   // covers n = n4*4 .. n4*4+3
    const int bp = tid >> 3;                  // batch pair
    const int b0 = bp*2, b1 = b0 + 1;
    const int gate_c = n4 >> 1, jj0 = (n4 & 1)*4;

    // load + transpose this block's w_hh slice into smem ONCE
    for (int u = tid; u < 32*Hv; u += NT) {
        int k = u & (Hv-1), n = u >> 10;
        int gate = n >> 3, jj = n & 7;
        WhT[k*WT_STRIDE + n] = w_hh[(size_t)(gate*Hv + j0 + jj)*Hv + k];
    }
    for (int u = tid; u < Bv*8; u += NT) csm[u] = 0.f;
    __syncthreads();

    for (int t = 0; t < Pv; t++) {
        float acc0[4] = {0.f,0.f,0.f,0.f};
        float acc1[4] = {0.f,0.f,0.f,0.f};
        // prefetch precomputed input-gate contribution
        const float4 gin0 = *(const float4*)&g_Gin[(size_t)(t*Bv + b0)*G4 + gate_c*Hv + j0 + jj0];
        const float4 gin1 = *(const float4*)&g_Gin[(size_t)(t*Bv + b1)*G4 + gate_c*Hv + j0 + jj0];

        if (t > 0) {
            const float* hprev = g_HS + (size_t)(t-1)*Bv*Hv;
            for (int k0 = 0; k0 < Hv; k0 += KT) {
                __syncthreads();
                for (int u = tid; u < Bv*(KT/4); u += NT) {
                    int r = u >> 5, c4 = u & 31;
                    *(float4*)&Hs[r*HS_STRIDE + c4*4] =
                        *(const float4*)&hprev[(size_t)r*Hv + k0 + c4*4];
                }
                __syncthreads();
                #pragma unroll 4
                for (int kk = 0; kk < KT; kk += 4) {
                    float4 a0 = *(const float4*)&Hs[b0*HS_STRIDE + kk];
                    float4 a1 = *(const float4*)&Hs[b1*HS_STRIDE + kk];
                    float4 w0 = *(const float4*)&WhT[(k0+kk+0)*WT_STRIDE + n4*4];
                    float4 w1 = *(const float4*)&WhT[(k0+kk+1)*WT_STRIDE + n4*4];
                    float4 w2 = *(const float4*)&WhT[(k0+kk+2)*WT_STRIDE + n4*4];
                    float4 w3 = *(const float4*)&WhT[(k0+kk+3)*WT_STRIDE + n4*4];
                    acc0[0] += a0.x*w0.x + a0.y*w1.x + a0.z*w2.x + a0.w*w3.x;
                    acc0[1] += a0.x*w0.y + a0.y*w1.y + a0.z*w2.y + a0.w*w3.y;
                    acc0[2] += a0.x*w0.z + a0.y*w1.z + a0.z*w2.z + a0.w*w3.z;
                    acc0[3] += a0.x*w0.w + a0.y*w1.w + a0.z*w2.w + a0.w*w3.w;
                    acc1[0] += a1.x*w0.x + a1.y*w1.x + a1.z*w2.x + a1.w*w3.x;
                    acc1[1] += a1.x*w0.y + a1.y*w1.y + a1.z*w2.y + a1.w*w3.y;
                    acc1[2] += a1.x*w0.z + a1.y*w1.z + a1.z*w2.z + a1.w*w3.z;
                    acc1[3] += a1.x*w0.w + a1.y*w1.w + a1.z*w2.w + a1.w*w3.w;
                }
            }
        }
        __syncthreads();
        gsm[b0*GS_STRIDE + n4*4+0] = acc0[0] + gin0.x;
        gsm[b0*GS_STRIDE + n4*4+1] = acc0[1] + gin0.y;
        gsm[b0*GS_STRIDE + n4*4+2] = acc0[2] + gin0.z;
        gsm[b0*GS_STRIDE + n4*4+3] = acc0[3] + gin0.w;
        gsm[b1*GS_STRIDE + n4*4+0] = acc1[0] + gin1.x;
        gsm[b1*GS_STRIDE + n4*4+1] = acc1[1] + gin1.y;
        gsm[b1*GS_STRIDE + n4*4+2] = acc1[2] + gin1.z;
        gsm[b1*GS_STRIDE + n4*4+3] = acc1[3] + gin1.w;
        __syncthreads();

        // activations + state update (512 outputs / 256 threads)
        #pragma unroll
        for (int m = tid; m < Bv*8; m += NT) {
            int b = m >> 3, jj = m & 7;
            float iv = gsm[b*GS_STRIDE + jj];
            float fv = gsm[b*GS_STRIDE + 8  + jj];
            float gv = gsm[b*GS_STRIDE + 16 + jj];
            float ov = gsm[b*GS_STRIDE + 24 + jj];
            float is = 1.f/(1.f + expf(-iv));
            float fs = 1.f/(1.f + expf(-fv));
            float gs = tanhf(gv);
            float os = 1.f/(1.f + expf(-ov));
            float cc = fs*csm[b*8 + jj] + is*gs;
            csm[b*8 + jj] = cc;
            g_HS[(size_t)t*Bv*Hv + (size_t)b*Hv + j0 + jj] = os*tanhf(cc);
        }
        __syncthreads();

        // grid-wide barrier (all 128 CTAs co-resident: 1 CTA/SM by smem)
        if (t < Pv-1) {
            if (tid == 0) {
                __threadfence();
                unsigned a = atomicAdd(&g_cnt, 1u);
                unsigned target = (unsigned)(t + 1);
                if (a == NB - 1) {
                    g_cnt = 0u;
                    __threadfence();
                    atomicAdd((unsigned*)&g_gen, 1u);
                } else {
                    while (g_gen < target) { }
                    __threadfence();
                }
            }
            __syncthreads();
        }
    }
}

// ---- head: tag_space (HS flat row = b*80+p per faithful reshape) ----------
__global__ void k_tag(const float* __restrict__ out_w, const float* __restrict__ out_b) {
    __shared__ float hrow[Hv];
    int bp = blockIdx.x;
    int tid = threadIdx.x;
    for (int u = tid; u < Hv; u += 256) hrow[u] = g_HS[(size_t)bp*Hv + u];
    __syncthreads();
    int warp = tid >> 5, lane = tid & 31;
    for (int tg = warp; tg < TAGSv; tg += 8) {
        float s = 0.f;
        for (int k = lane; k < Hv; k += 32) s += hrow[k]*out_w[(size_t)tg*Hv + k];
        #pragma unroll
        for (int o = 16; o; o >>= 1) s += __shfl_down_sync(0xffffffffu, s, o);
        if (lane == 0) g_TS[bp*TAGSv + tg] = s + out_b[tg];
    }
}

// ---- log_softmax over P axis ----------------------------------------------
__global__ void k_lsm(float* __restrict__ out) {
    int b = blockIdx.x;
    int tg = threadIdx.x;
    if (tg >= TAGSv) return;
    float mx = -1e30f;
    for (int p = 0; p < Pv; p++)
        mx = fmaxf(mx, g_TS[(b*Pv + p)*TAGSv + tg]);
    float s = 0.f;
    for (int p = 0; p < Pv; p++)
        s += expf(g_TS[(b*Pv + p)*TAGSv + tg] - mx);
    float l = mx + logf(s);
    for (int p = 0; p < Pv; p++)
        out[(size_t)(b*Pv + p)*TAGSv + tg] = g_TS[(b*Pv + p)*TAGSv + tg] - l;
}

// ---------------------------------------------------------------------------
extern "C" void kernel_launch(void* const* d_in, const int* in_sizes, int n_in,
                              void* d_out, int out_size) {
    const int*   sent  = (const int*)  d_in[0];
    const int*   chars = (const int*)  d_in[1];
    const float* wemb  = (const float*)d_in[2];
    const float* cemb  = (const float*)d_in[3];
    const float* convw = (const float*)d_in[4];
    const float* convb = (const float*)d_in[5];
    const float* w_ih  = (const float*)d_in[6];
    const float* w_hh  = (const float*)d_in[7];
    const float* b_ih  = (const float*)d_in[8];
    const float* b_hh  = (const float*)d_in[9];
    const float* out_w = (const float*)d_in[10];
    const float* out_b = (const float*)d_in[11];
    float* out = (float*)d_out;

    static int smem_set = 0;
    const int SMEM = (Hv*WT_STRIDE + Bv*HS_STRIDE + Bv*GS_STRIDE + Bv*8) * 4;
    if (!smem_set) {
        cudaFuncSetAttribute(k_lstm, cudaFuncAttributeMaxDynamicSharedMemorySize, SMEM);
        smem_set = 1;
    }

    k_init<<<1, 32>>>();
    k_embed<<<ROWS, 128>>>(sent, chars, wemb, cemb, convw, convb);
    dim3 g2(G4/64, ROWS/64);
    k_ingemm<<<g2, 256>>>(w_ih, b_ih, b_hh);
    k_lstm<<<NB, NT, SMEM>>>(w_hh);
    k_tag<<<ROWS, 256>>>(out_w, out_b);
    k_lsm<<<Bv, 64>>>(out);
}

// round 4
// speedup vs baseline: 4.3383x; 2.3447x over previous
#include <cuda_runtime.h>
#include <cuda_bf16.h>
#include <math.h>
#include <stdint.h>

#define Bv 64
#define Pv 80
#define LCv 18
#define Ev 256
#define Kw 3
#define WNv 16
#define LCHv 4
#define Hv 1024
#define Dv 260
#define TAGSv 50
#define ROWS (Bv*Pv)      /* 5120 */
#define G4 (4*Hv)         /* 4096 */

// persistent LSTM config
#define NB 128
#define NT 256
#define AW_STRIDE 516     /* A row stride in 32-bit words (1032 bf16, conflict-free) */
#define WW_STRIDE 516
#define RED_STRIDE 17

// ---- scratch ----
__device__ float g_X[ROWS*Dv];
__device__ float g_Gin[(size_t)ROWS*G4];
__device__ __nv_bfloat16 g_HSb[(size_t)ROWS*Hv];
__device__ float g_TS[ROWS*TAGSv];
__device__ unsigned g_cnt;
__device__ volatile unsigned g_gen;

// ---------------------------------------------------------------------------
__global__ void k_init() {
    if (blockIdx.x == 0 && threadIdx.x == 0) { g_cnt = 0u; g_gen = 0u; }
}

// ---- embedding + char CNN -------------------------------------------------
__global__ void k_embed(const int* __restrict__ sent, const int* __restrict__ chars,
                        const float* __restrict__ wemb, const float* __restrict__ cemb,
                        const float* __restrict__ convw, const float* __restrict__ convb) {
    __shared__ float ce[LCv*Ev];
    __shared__ float phi[WNv*LCHv];
    int bp = blockIdx.x;
    int tid = threadIdx.x;

    for (int u = tid; u < LCv*Ev; u += 128) {
        int l = u >> 8, e = u & 255;
        int ci = chars[bp*LCv + l];
        ce[u] = cemb[(size_t)ci*Ev + e];
    }
    __syncthreads();

    int wi = sent[bp];
    for (int e = tid; e < Ev; e += 128)
        g_X[(size_t)bp*Dv + e] = wemb[(size_t)wi*Ev + e];

    if (tid < WNv*LCHv) {
        int w = tid >> 2, c = tid & 3;
        float s = convb[c];
        #pragma unroll
        for (int k = 0; k < Kw; k++) {
            const float* cw = convw + c*(Kw*Ev) + k*Ev;
            const float* cc = ce + (w + k)*Ev;
            for (int e = 0; e < Ev; e++) s += cc[e]*cw[e];
        }
        phi[w*LCHv + c] = s;
    }
    __syncthreads();
    if (tid < LCHv) {
        float m = -1e30f;
        for (int w = 0; w < WNv; w++) m = fmaxf(m, phi[w*LCHv + tid]);
        g_X[(size_t)bp*Dv + Ev + tid] = m;
    }
}

// ---- input GEMM (fp32): Gin = X @ w_ih^T + b_ih + b_hh --------------------
__global__ void k_ingemm(const float* __restrict__ w_ih,
                         const float* __restrict__ b_ih,
                         const float* __restrict__ b_hh) {
    __shared__ float Xs[64][33];
    __shared__ float Ws[64][33];
    int i0 = blockIdx.y * 64;
    int j0 = blockIdx.x * 64;
    int tid = threadIdx.x, tx = tid & 15, ty = tid >> 4;
    float acc[4][4] = {};

    for (int k0 = 0; k0 < Dv; k0 += 32) {
        for (int u = tid; u < 64*32; u += 256) {
            int r = u >> 5, kk = u & 31, k = k0 + kk;
            Xs[r][kk] = (k < Dv) ? g_X[(size_t)(i0 + r)*Dv + k] : 0.f;
            Ws[r][kk] = (k < Dv) ? w_ih[(size_t)(j0 + r)*Dv + k] : 0.f;
        }
        __syncthreads();
        #pragma unroll
        for (int kk = 0; kk < 32; kk++) {
            float a0 = Xs[ty*4+0][kk], a1 = Xs[ty*4+1][kk],
                  a2 = Xs[ty*4+2][kk], a3 = Xs[ty*4+3][kk];
            float w0 = Ws[tx*4+0][kk], w1 = Ws[tx*4+1][kk],
                  w2 = Ws[tx*4+2][kk], w3 = Ws[tx*4+3][kk];
            acc[0][0]+=a0*w0; acc[0][1]+=a0*w1; acc[0][2]+=a0*w2; acc[0][3]+=a0*w3;
            acc[1][0]+=a1*w0; acc[1][1]+=a1*w1; acc[1][2]+=a1*w2; acc[1][3]+=a1*w3;
            acc[2][0]+=a2*w0; acc[2][1]+=a2*w1; acc[2][2]+=a2*w2; acc[2][3]+=a2*w3;
            acc[3][0]+=a3*w0; acc[3][1]+=a3*w1; acc[3][2]+=a3*w2; acc[3][3]+=a3*w3;
        }
        __syncthreads();
    }
    #pragma unroll
    for (int ii = 0; ii < 4; ii++)
        #pragma unroll
        for (int jj = 0; jj < 4; jj++) {
            int j = j0 + tx*4 + jj;
            g_Gin[(size_t)(i0 + ty*4 + ii)*G4 + j] = acc[ii][jj] + b_ih[j] + b_hh[j];
        }
}

// ---- persistent tensor-core LSTM ------------------------------------------
// CTA bx owns h-cols [bx*8, bx*8+8) => 32 gate cols (n = gate*8+jj).
// Per step per CTA: D[64,32] = h_prev[64,1024] @ Wslice^T, via mma.m16n8k16 bf16.
// Warps: (warp&3) = m-tile (16 rows), (warp>>2) = K half (512). Tile nt == gate.
__global__ void __launch_bounds__(NT, 1) k_lstm(const float* __restrict__ w_hh) {
    extern __shared__ uint32_t smw[];
    uint32_t* Aw  = smw;                               // h_prev bf16 [64][1032]
    uint32_t* Ww  = smw + 64*AW_STRIDE;                // W bf16 [32][1032]
    float*    Red = (float*)(smw + 64*AW_STRIDE + 32*WW_STRIDE);

    const int tid  = threadIdx.x;
    const int warp = tid >> 5, lane = tid & 31;
    const int gid  = lane >> 2, tig = lane & 3;
    const int j0   = blockIdx.x * 8;
    const int m0   = (warp & 3) * 16;
    const int kbw  = (warp >> 2) * 256;                // k-half offset in words

    // load + convert W slice to bf16 once (row n=gate*8+jj, contiguous k)
    {
        __nv_bfloat16* Whh = (__nv_bfloat16*)Ww;
        for (int u = tid; u < 32*Hv; u += NT) {
            int n = u >> 10, k = u & (Hv-1);
            int gate = n >> 3, jj = n & 7;
            Whh[n*(2*WW_STRIDE) + k] =
                __float2bfloat16(w_hh[(size_t)(gate*Hv + j0 + jj)*Hv + k]);
        }
    }
    __syncthreads();

    float creg[4] = {0.f, 0.f, 0.f, 0.f};

    for (int t = 0; t < Pv; t++) {
        float d[16];
        #pragma unroll
        for (int i = 0; i < 16; i++) d[i] = 0.f;

        // prefetch precomputed input-gate contributions (fp32, exact)
        float2 gin[8];
        if (warp < 4) {
            #pragma unroll
            for (int nt = 0; nt < 4; nt++)
                #pragma unroll
                for (int r = 0; r < 2; r++)
                    gin[nt*2+r] = *(const float2*)
                        &g_Gin[(size_t)(t*Bv + m0 + gid + r*8)*G4 + nt*Hv + j0 + tig*2];
        }

        if (t > 0) {
            // stage h_{t-1} (bf16) into smem A
            __syncthreads();
            const uint4* src = (const uint4*)(g_HSb + (size_t)(t-1)*Bv*Hv);
            __nv_bfloat16* Ah = (__nv_bfloat16*)Aw;
            for (int u = tid; u < 64*128; u += NT) {
                int r = u >> 7, c = u & 127;
                *(uint4*)(Ah + r*(2*AW_STRIDE) + c*8) = src[r*128 + c];
            }
            __syncthreads();

            const uint32_t ar0 = (uint32_t)(m0 + gid)*AW_STRIDE + kbw + tig;
            const uint32_t ar1 = ar0 + 8*AW_STRIDE;
            #pragma unroll 2
            for (int kc = 0; kc < 32; kc++) {
                uint32_t kw = kc*8;
                uint32_t a0 = Aw[ar0 + kw];
                uint32_t a2 = Aw[ar0 + kw + 4];
                uint32_t a1 = Aw[ar1 + kw];
                uint32_t a3 = Aw[ar1 + kw + 4];
                #pragma unroll
                for (int nt = 0; nt < 4; nt++) {
                    uint32_t wr = (uint32_t)(nt*8 + gid)*WW_STRIDE + kbw + kw + tig;
                    uint32_t b0 = Ww[wr];
                    uint32_t b1 = Ww[wr + 4];
                    asm volatile(
                        "mma.sync.aligned.m16n8k16.row.col.f32.bf16.bf16.f32 "
                        "{%0,%1,%2,%3}, {%4,%5,%6,%7}, {%8,%9}, {%0,%1,%2,%3};\n"
                        : "+f"(d[nt*4+0]), "+f"(d[nt*4+1]),
                          "+f"(d[nt*4+2]), "+f"(d[nt*4+3])
                        : "r"(a0), "r"(a1), "r"(a2), "r"(a3), "r"(b0), "r"(b1));
                }
            }

            // reduce the two K halves
            if (warp >= 4) {
                float* rw = Red + (warp-4)*32*RED_STRIDE + lane*RED_STRIDE;
                #pragma unroll
                for (int i = 0; i < 16; i++) rw[i] = d[i];
            }
            __syncthreads();
            if (warp < 4) {
                const float* rr = Red + warp*32*RED_STRIDE + lane*RED_STRIDE;
                #pragma unroll
                for (int i = 0; i < 16; i++) d[i] += rr[i];
            }
        }

        // activations + state update: fully register-local per thread
        if (warp < 4) {
            __nv_bfloat16* hdst = g_HSb + (size_t)(t*Bv)*Hv;
            #pragma unroll
            for (int r = 0; r < 2; r++) {
                float h01[2];
                #pragma unroll
                for (int p = 0; p < 2; p++) {
                    int idx = r*2 + p;
                    float iv = d[idx]      + ((p==0) ? gin[r].x   : gin[r].y);
                    float fv = d[4 + idx]  + ((p==0) ? gin[2+r].x : gin[2+r].y);
                    float gv = d[8 + idx]  + ((p==0) ? gin[4+r].x : gin[4+r].y);
                    float ov = d[12 + idx] + ((p==0) ? gin[6+r].x : gin[6+r].y);
                    float is = 1.f/(1.f + expf(-iv));
                    float fs = 1.f/(1.f + expf(-fv));
                    float gs = tanhf(gv);
                    float os = 1.f/(1.f + expf(-ov));
                    float cc = fs*creg[idx] + is*gs;
                    creg[idx] = cc;
                    h01[p] = os*tanhf(cc);
                }
                int row = m0 + gid + r*8;
                __nv_bfloat162 hv;
                hv.x = __float2bfloat16(h01[0]);
                hv.y = __float2bfloat16(h01[1]);
                *(__nv_bfloat162*)&hdst[(size_t)row*Hv + j0 + tig*2] = hv;
            }
        }

        // grid-wide barrier
        if (t < Pv - 1) {
            __threadfence();
            __syncthreads();
            if (tid == 0) {
                unsigned a = atomicAdd(&g_cnt, 1u);
                unsigned target = (unsigned)(t + 1);
                if (a == NB - 1) {
                    g_cnt = 0u;
                    __threadfence();
                    atomicAdd((unsigned*)&g_gen, 1u);
                } else {
                    while (g_gen < target) { }
                    __threadfence();
                }
            }
            __syncthreads();
        }
    }
}

// ---- head (reads bf16 h) --------------------------------------------------
__global__ void k_tag(const float* __restrict__ out_w, const float* __restrict__ out_b) {
    __shared__ float hrow[Hv];
    int bp = blockIdx.x;
    int tid = threadIdx.x;
    for (int u = tid; u < Hv; u += 256)
        hrow[u] = __bfloat162float(g_HSb[(size_t)bp*Hv + u]);
    __syncthreads();
    int warp = tid >> 5, lane = tid & 31;
    for (int tg = warp; tg < TAGSv; tg += 8) {
        float s = 0.f;
        for (int k = lane; k < Hv; k += 32) s += hrow[k]*out_w[(size_t)tg*Hv + k];
        #pragma unroll
        for (int o = 16; o; o >>= 1) s += __shfl_down_sync(0xffffffffu, s, o);
        if (lane == 0) g_TS[bp*TAGSv + tg] = s + out_b[tg];
    }
}

// ---- log_softmax over P ---------------------------------------------------
__global__ void k_lsm(float* __restrict__ out) {
    int b = blockIdx.x;
    int tg = threadIdx.x;
    if (tg >= TAGSv) return;
    float mx = -1e30f;
    for (int p = 0; p < Pv; p++)
        mx = fmaxf(mx, g_TS[(b*Pv + p)*TAGSv + tg]);
    float s = 0.f;
    for (int p = 0; p < Pv; p++)
        s += expf(g_TS[(b*Pv + p)*TAGSv + tg] - mx);
    float l = mx + logf(s);
    for (int p = 0; p < Pv; p++)
        out[(size_t)(b*Pv + p)*TAGSv + tg] = g_TS[(b*Pv + p)*TAGSv + tg] - l;
}

// ---------------------------------------------------------------------------
extern "C" void kernel_launch(void* const* d_in, const int* in_sizes, int n_in,
                              void* d_out, int out_size) {
    const int*   sent  = (const int*)  d_in[0];
    const int*   chars = (const int*)  d_in[1];
    const float* wemb  = (const float*)d_in[2];
    const float* cemb  = (const float*)d_in[3];
    const float* convw = (const float*)d_in[4];
    const float* convb = (const float*)d_in[5];
    const float* w_ih  = (const float*)d_in[6];
    const float* w_hh  = (const float*)d_in[7];
    const float* b_ih  = (const float*)d_in[8];
    const float* b_hh  = (const float*)d_in[9];
    const float* out_w = (const float*)d_in[10];
    const float* out_b = (const float*)d_in[11];
    float* out = (float*)d_out;

    const int SMEM = (64*AW_STRIDE + 32*WW_STRIDE)*4 + 4*32*RED_STRIDE*4;
    static int smem_set = 0;
    if (!smem_set) {
        cudaFuncSetAttribute(k_lstm, cudaFuncAttributeMaxDynamicSharedMemorySize, SMEM);
        smem_set = 1;
    }

    k_init<<<1, 32>>>();
    k_embed<<<ROWS, 128>>>(sent, chars, wemb, cemb, convw, convb);
    dim3 g2(G4/64, ROWS/64);
    k_ingemm<<<g2, 256>>>(w_ih, b_ih, b_hh);
    k_lstm<<<NB, NT, SMEM>>>(w_hh);
    k_tag<<<ROWS, 256>>>(out_w, out_b);
    k_lsm<<<Bv, 64>>>(out);
}